// round 10
// baseline (speedup 1.0000x reference)
#include <cuda_runtime.h>
#include <math.h>
#include <float.h>
#include <stdint.h>

#define NB 16
#define NA 5
#define NH 96
#define NW 96
#define MAXT 50
#define NCLS 40
#define CH (5 + NCLS)          // 45
#define NCELL (NB*NA*NH*NW)    // 737280
#define PLANE (NH*NW)          // 9216
#define MAXE 304

#define CORR_BLOCKS 8
#define MAIN_THREADS 256
#define CELLS_PER_CHUNK 256
#define CHUNK_BYTES (CELLS_PER_CHUNK * CH * 4)     // 46080
#define CHUNKS_PER_BLOCK 4
#define CELLS_PER_BLOCK (CELLS_PER_CHUNK * CHUNKS_PER_BLOCK)  // 1024
#define SWEEP_BLOCKS (NCELL / CELLS_PER_BLOCK)     // 720 exact
#define TOTAL_BLOCKS (CORR_BLOCKS + SWEEP_BLOCKS)
#define WARPS_PER_BLOCK (MAIN_THREADS / 32)
#define DYN_SMEM (2 * CHUNK_BYTES)                 // 92160

// Compact correction list
__device__ int   g_ecnt[NB];
__device__ int   g_ecell[NB * MAXE];
__device__ int   g_einfo[NB * MAXE];   // bit0: m, bit1: cm, bits2+: label
__device__ float g_etx[NB * MAXE];
__device__ float g_ety[NB * MAXE];
__device__ float g_etw[NB * MAXE];
__device__ float g_eth[NB * MAXE];
__device__ float g_nGT[NB];
__device__ float g_nC[NB];
// acc: 0 sx,1 sy,2 sw,3 sh,4 neg_sum,5 neg_cnt_delta,6 pos_sum,7 nM,8 cls_sum,9 nProp
__device__ float g_acc[12];
__device__ int   g_done;

__device__ __forceinline__ uint32_t smem_u32(const void* p) {
    return (uint32_t)__cvta_generic_to_shared(p);
}

__device__ __forceinline__ void mbar_init(uint32_t mb, uint32_t count) {
    asm volatile("mbarrier.init.shared::cta.b64 [%0], %1;" :: "r"(mb), "r"(count) : "memory");
}

__device__ __forceinline__ void tma_fetch(uint32_t dst, const void* src, uint32_t bytes, uint32_t mb) {
    asm volatile("mbarrier.arrive.expect_tx.shared::cta.b64 _, [%0], %1;"
                 :: "r"(mb), "r"(bytes) : "memory");
    asm volatile("cp.async.bulk.shared::cta.global.mbarrier::complete_tx::bytes [%0], [%1], %2, [%3];"
                 :: "r"(dst), "l"(src), "r"(bytes), "r"(mb) : "memory");
}

__device__ __forceinline__ void mbar_wait(uint32_t mb, uint32_t parity) {
    uint32_t done;
    asm volatile(
        "{\n\t"
        ".reg .pred p;\n\t"
        "mbarrier.try_wait.parity.acquire.cta.shared::cta.b64 p, [%1], %2;\n\t"
        "selp.b32 %0, 1, 0, p;\n\t"
        "}" : "=r"(done) : "r"(mb), "r"(parity) : "memory");
    if (!done) {
        asm volatile(
            "{\n\t"
            ".reg .pred P1;\n\t"
            "WAIT_LOOP_%=:\n\t"
            "mbarrier.try_wait.parity.acquire.cta.shared::cta.b64 P1, [%0], %1, 0x989680;\n\t"
            "@P1 bra.uni WAIT_DONE_%=;\n\t"
            "bra.uni WAIT_LOOP_%=;\n\t"
            "WAIT_DONE_%=:\n\t"
            "}" :: "r"(mb), "r"(parity) : "memory");
    }
}

__global__ void __launch_bounds__(64) k_build(const float* __restrict__ pred,
                                              const float* __restrict__ target,
                                              const int*   __restrict__ tsizes) {
    const int b = blockIdx.x;
    const int t = threadIdx.x;

    __shared__ int   pos_map[PLANE];
    __shared__ int   lastBest[MAXT * NA];
    __shared__ int   lastIgn[MAXT * NA];
    __shared__ int   s_gi[MAXT], s_gj[MAXT], s_lbl[MAXT], s_cor[MAXT];
    __shared__ float s_tx[MAXT], s_ty[MAXT], s_tw[MAXT], s_th[MAXT];
    __shared__ int   s_cnt;

    if (t == 0) s_cnt = 0;
    if (b == 0) {
        if (t < 12) g_acc[t] = 0.0f;
        if (t == 12) g_done = 0;
    }
    for (int i = t; i < PLANE; i += 64) pos_map[i] = 0x7FFFFFFF;
    for (int i = t; i < MAXT * NA; i += 64) { lastBest[i] = -1; lastIgn[i] = -1; }
    __syncthreads();

    int ts = tsizes[b];
    if (ts > MAXT) ts = MAXT;

    const float AW[5] = {1.f, 2.f, 4.f, 2.f, 4.f};
    const float AH[5] = {1.f, 2.f, 4.f, 4.f, 2.f};

    if (t < ts) {
        const float* row = target + ((long)(b * MAXT + t)) * (13 + NCLS);
        float gx = row[0] * (1.0f / 16.0f);
        float gy = row[1] * (1.0f / 16.0f);
        float gh = row[3] * (1.0f / 16.0f);
        float gw = row[4] * (1.0f / 16.0f);
        int gi = (int)gx;
        int gj = (int)gy;
        int pos = gj * NW + gi;

        atomicMin(&pos_map[pos], t);

        int lbl = 0; float bv = row[13];
        #pragma unroll
        for (int c = 1; c < NCLS; c++) {
            float v = row[13 + c];
            if (v > bv) { bv = v; lbl = c; }
        }

        float garea = (gw + 1.0f) * (gh + 1.0f);
        float best_iou = -1.0f; int best = 0; unsigned ign = 0u;
        #pragma unroll
        for (int a = 0; a < 5; a++) {
            float iw = fmaxf(fminf(gw, AW[a]) + 1.0f, 0.0f);
            float ih = fmaxf(fminf(gh, AH[a]) + 1.0f, 0.0f);
            float inter = iw * ih;
            float aa = (AW[a] + 1.0f) * (AH[a] + 1.0f);
            float iou = inter / (garea + aa - inter + 1e-16f);
            if (iou > 0.5f) ign |= (1u << a);
            if (iou > best_iou) { best_iou = iou; best = a; }  // first-max tie
        }

        s_gi[t] = gi; s_gj[t] = gj; s_lbl[t] = lbl;
        s_tx[t] = gx - (float)gi;
        s_ty[t] = gy - (float)gj;
        s_tw[t] = logf(gw / AW[best] + 1e-16f);
        s_th[t] = logf(gh / AH[best] + 1e-16f);
        s_cor[t] = (int)ign | (best << 8) | (pos << 16);

        long base = ((((long)b * NA + best) * NH + gj) * NW + gi) * CH;
        float pc = pred[base + 0];
        float x = pred[base + 1], y = pred[base + 2];
        float h = pred[base + 3], w = pred[base + 4];
        float px = x + (float)gi, py = y + (float)gj;
        float pw = expf(w) * AW[best];
        float ph = expf(h) * AH[best];

        float gx1 = gx - gw * 0.5f, gx2 = gx + gw * 0.5f;
        float gy1 = gy - gh * 0.5f, gy2 = gy + gh * 0.5f;
        float px1 = px - pw * 0.5f, px2 = px + pw * 0.5f;
        float py1 = py - ph * 0.5f, py2 = py + ph * 0.5f;
        float iw2 = fmaxf(fminf(gx2, px2) - fmaxf(gx1, px1) + 1.0f, 0.0f);
        float ih2 = fmaxf(fminf(gy2, py2) - fmaxf(gy1, py1) + 1.0f, 0.0f);
        float inter2 = iw2 * ih2;
        float ga = (gx2 - gx1 + 1.0f) * (gy2 - gy1 + 1.0f);
        float pa = (px2 - px1 + 1.0f) * (py2 - py1 + 1.0f);
        float iou2 = inter2 / (ga + pa - inter2 + 1e-16f);

        int cb = 0; float cbv = pred[base + 5];
        #pragma unroll
        for (int c = 1; c < NCLS; c++) {
            float v = pred[base + 5 + c];
            if (v > cbv) { cbv = v; cb = c; }
        }
        int correct = (iou2 > 0.5f && cb == lbl && pc > 0.5f) ? 1 : 0;
        s_cor[t] |= (correct << 30);
    }
    __syncthreads();

    if (t < ts) {
        int pk   = s_cor[t];
        int pos  = (pk >> 16) & 0x3FFF;
        int best = (pk >> 8) & 0x1F;
        unsigned ign = (unsigned)(pk & 0xFF);
        int slot = pos_map[pos];
        atomicMax(&lastBest[slot * NA + best], t);
        #pragma unroll
        for (int a = 0; a < 5; a++)
            if ((ign >> a) & 1u) atomicMax(&lastIgn[slot * NA + a], t);
    }
    __syncthreads();

    if (t < ts) {
        int pos = s_gj[t] * NW + s_gi[t];
        if (pos_map[pos] == t) {
            #pragma unroll
            for (int a = 0; a < 5; a++) {
                int lb = lastBest[t * NA + a];
                int li = lastIgn[t * NA + a];
                if (lb >= 0) {
                    int cm = (lb >= li) ? 1 : 0;
                    int idx = atomicAdd(&s_cnt, 1);
                    int gidx = b * MAXE + idx;
                    g_ecell[gidx] = b * (NA * PLANE) + a * PLANE + pos;
                    g_einfo[gidx] = 1 | (cm << 1) | (s_lbl[lb] << 2);
                    g_etx[gidx] = s_tx[lb]; g_ety[gidx] = s_ty[lb];
                    g_etw[gidx] = s_tw[lb]; g_eth[gidx] = s_th[lb];
                } else if (li >= 0) {
                    int idx = atomicAdd(&s_cnt, 1);
                    int gidx = b * MAXE + idx;
                    g_ecell[gidx] = b * (NA * PLANE) + a * PLANE + pos;
                    g_einfo[gidx] = 0;
                }
            }
        }
    }
    __syncthreads();

    if (t == 0) {
        g_ecnt[b] = s_cnt;
        int nC = 0;
        for (int i = 0; i < ts; i++) nC += (s_cor[i] >> 30) & 1;
        g_nGT[b] = (float)ts;
        g_nC[b]  = (float)nC;
    }
}

__global__ void __launch_bounds__(MAIN_THREADS) k_main(const float* __restrict__ pred,
                                                       float* __restrict__ out) {
    extern __shared__ float dynbuf[];              // 2 x CHUNK_BYTES
    __shared__ float red[WARPS_PER_BLOCK][10];
    __shared__ unsigned long long mbar[2];
    const int lane = threadIdx.x & 31;
    const int warp = threadIdx.x >> 5;
    const int t = threadIdx.x;

    if (blockIdx.x >= CORR_BLOCKS) {
        // ---- TMA bulk-copy pipeline sweep: 1024 cells/block, 4 chunks, 2 buffers ----
        const int sb = blockIdx.x - CORR_BLOCKS;
        const char* src = (const char*)pred + (size_t)sb * (CELLS_PER_BLOCK * CH * 4);
        float* buf0 = dynbuf;
        float* buf1 = dynbuf + CHUNK_BYTES / 4;
        uint32_t d0 = smem_u32(buf0);
        uint32_t d1 = smem_u32(buf1);
        uint32_t mb0 = smem_u32(&mbar[0]);
        uint32_t mb1 = smem_u32(&mbar[1]);

        if (t == 0) { mbar_init(mb0, 1); mbar_init(mb1, 1); }
        __syncthreads();
        asm volatile("fence.proxy.async.shared::cta;" ::: "memory");

        if (t == 0) {
            tma_fetch(d0, src + 0 * CHUNK_BYTES, CHUNK_BYTES, mb0);
            tma_fetch(d1, src + 1 * CHUNK_BYTES, CHUNK_BYTES, mb1);
        }

        float neg = 0.0f, np = 0.0f;
        const int soff = t * CH;       // float idx of this thread's cell: bank 13t mod 32, conflict-free

        // chunk 0 (buf0, phase 0)
        mbar_wait(mb0, 0);
        { float c = buf0[soff]; neg += fmaxf(c,0.0f) + log1pf(expf(-fabsf(c))); np += (c>0.0f)?1.0f:0.0f; }
        __syncthreads();
        if (t == 0) tma_fetch(d0, src + 2 * CHUNK_BYTES, CHUNK_BYTES, mb0);

        // chunk 1 (buf1, phase 0)
        mbar_wait(mb1, 0);
        { float c = buf1[soff]; neg += fmaxf(c,0.0f) + log1pf(expf(-fabsf(c))); np += (c>0.0f)?1.0f:0.0f; }
        __syncthreads();
        if (t == 0) tma_fetch(d1, src + 3 * CHUNK_BYTES, CHUNK_BYTES, mb1);

        // chunk 2 (buf0, phase 1)
        mbar_wait(mb0, 1);
        { float c = buf0[soff]; neg += fmaxf(c,0.0f) + log1pf(expf(-fabsf(c))); np += (c>0.0f)?1.0f:0.0f; }

        // chunk 3 (buf1, phase 1)
        mbar_wait(mb1, 1);
        { float c = buf1[soff]; neg += fmaxf(c,0.0f) + log1pf(expf(-fabsf(c))); np += (c>0.0f)?1.0f:0.0f; }

        #pragma unroll
        for (int off = 16; off > 0; off >>= 1) {
            neg += __shfl_down_sync(0xFFFFFFFFu, neg, off);
            np  += __shfl_down_sync(0xFFFFFFFFu, np, off);
        }
        if (lane == 0) { red[warp][0] = neg; red[warp][1] = np; }
        __syncthreads();
        if (t == 0) {
            float sn = 0.0f, sp = 0.0f;
            #pragma unroll
            for (int w = 0; w < WARPS_PER_BLOCK; w++) { sn += red[w][0]; sp += red[w][1]; }
            atomicAdd(&g_acc[4], sn);
            atomicAdd(&g_acc[9], sp);
        }
    } else {
        // ---- correction path: exact deltas vs default (m=0, cm=1) ----
        float acc[10];
        #pragma unroll
        for (int k = 0; k < 10; k++) acc[k] = 0.0f;

        const int tid = blockIdx.x * MAIN_THREADS + threadIdx.x;
        const int stride = CORR_BLOCKS * MAIN_THREADS;
        for (int b = 0; b < NB; b++) {
            int cnt = g_ecnt[b];
            for (int i = tid; i < cnt; i += stride) {
                int gidx = b * MAXE + i;
                int cell = g_ecell[gidx];
                int info = g_einfo[gidx];
                const float* p = pred + (size_t)cell * CH;
                float pc = p[0];
                float bce0 = fmaxf(pc, 0.0f) + log1pf(expf(-fabsf(pc)));
                if (info & 1) {
                    float bce1 = bce0 - pc;
                    if ((info >> 1) & 1) { acc[4] -= bce0; acc[5] -= 1.0f; }
                    else                 { acc[4] += bce1 - bce0; }
                    acc[6] += bce1;
                    acc[7] += 1.0f;
                    float dx = p[1] - g_etx[gidx]; acc[0] += dx * dx;
                    float dy = p[2] - g_ety[gidx]; acc[1] += dy * dy;
                    float dw = p[4] - g_etw[gidx]; acc[2] += dw * dw;
                    float dh = p[3] - g_eth[gidx]; acc[3] += dh * dh;
                    int lbl = info >> 2;
                    float mx = -FLT_MAX;
                    for (int c = 0; c < NCLS; c++) mx = fmaxf(mx, p[5 + c]);
                    float sxp = 0.0f;
                    for (int c = 0; c < NCLS; c++) sxp += expf(p[5 + c] - mx);
                    acc[8] += -(p[5 + lbl] - mx - logf(sxp));
                } else {
                    acc[4] -= bce0; acc[5] -= 1.0f;
                }
            }
        }

        #pragma unroll
        for (int k = 0; k < 10; k++) {
            float x = acc[k];
            #pragma unroll
            for (int off = 16; off > 0; off >>= 1)
                x += __shfl_down_sync(0xFFFFFFFFu, x, off);
            if (lane == 0) red[warp][k] = x;
        }
        __syncthreads();
        if (threadIdx.x == 0) {
            #pragma unroll
            for (int k = 0; k < 10; k++) {
                float x = 0.0f;
                #pragma unroll
                for (int w = 0; w < WARPS_PER_BLOCK; w++) x += red[w][k];
                if (x != 0.0f) atomicAdd(&g_acc[k], x);
            }
        }
    }

    // ---- last-block-done finalization ----
    if (threadIdx.x == 0) {
        __threadfence();
        int old = atomicAdd(&g_done, 1);
        if (old == TOTAL_BLOCKS - 1) {
            volatile float* A = g_acc;
            float nM = A[7];
            float lx = A[0] / nM, ly = A[1] / nM, lw = A[2] / nM, lh = A[3] / nM;
            float neg_cnt = (float)NCELL + A[5];
            float lconf = A[4] / neg_cnt + A[6] / nM;
            float lcls = (1.0f / (float)NB) * A[8] / nM;
            float nGT = 0.0f, nC = 0.0f;
            for (int b = 0; b < NB; b++) { nGT += g_nGT[b]; nC += g_nC[b]; }
            float nP = A[9];
            out[0] = lx + ly + lw + lh + lconf + lcls;
            out[1] = lx + ly + lw + lh;
            out[2] = lconf;
            out[3] = lcls;
            out[4] = nC / fmaxf(nGT, 1.0f);
            out[5] = (nP > 0.0f) ? (nC / fmaxf(nP, 1.0f)) : 1.0f;
        }
    }
}

extern "C" void kernel_launch(void* const* d_in, const int* in_sizes, int n_in,
                              void* d_out, int out_size) {
    const float* pred   = (const float*)d_in[0];
    const float* target = (const float*)d_in[1];
    const int*   tsz    = (const int*)d_in[2];
    float* out = (float*)d_out;
    (void)in_sizes; (void)n_in; (void)out_size;

    static int attr_set = 0;
    if (!attr_set) {
        cudaFuncSetAttribute(k_main, cudaFuncAttributeMaxDynamicSharedMemorySize, DYN_SMEM);
        attr_set = 1;
    }

    k_build<<<NB, 64>>>(pred, target, tsz);
    k_main<<<TOTAL_BLOCKS, MAIN_THREADS, DYN_SMEM>>>(pred, out);
}

// round 13
// speedup vs baseline: 1.4648x; 1.4648x over previous
#include <cuda_runtime.h>
#include <math.h>
#include <float.h>
#include <stdint.h>

#define NB 16
#define NA 5
#define NH 96
#define NW 96
#define MAXT 50
#define NCLS 40
#define CH (5 + NCLS)          // 45
#define NCELL (NB*NA*NH*NW)    // 737280
#define PLANE (NH*NW)          // 9216
#define MAXE 304

#define CORR_BLOCKS 8
#define MAIN_THREADS 256
#define SWEEP_BLOCKS (NCELL / MAIN_THREADS)     // 2880 exact, 1 cell/thread
#define TOTAL_BLOCKS (CORR_BLOCKS + SWEEP_BLOCKS)
#define WARPS_PER_BLOCK (MAIN_THREADS / 32)

// Compact correction list
__device__ int   g_ecnt[NB];
__device__ int   g_ecell[NB * MAXE];
__device__ int   g_einfo[NB * MAXE];   // bit0: m, bit1: cm, bits2+: label
__device__ float g_etx[NB * MAXE];
__device__ float g_ety[NB * MAXE];
__device__ float g_etw[NB * MAXE];
__device__ float g_eth[NB * MAXE];
__device__ float g_nGT[NB];
__device__ float g_nC[NB];
// acc: 0 sx,1 sy,2 sw,3 sh,4 neg_sum,5 neg_cnt_delta,6 pos_sum,7 nM,8 cls_sum,9 nProp
__device__ float g_acc[12];
__device__ int   g_done;

// Coherent-path global load (avoid ld.global.nc / __ldg, which plateaus on this box)
__device__ __forceinline__ float ldg_coherent(const float* p) {
    float v;
    asm volatile("ld.global.f32 %0, [%1];" : "=f"(v) : "l"(p));
    return v;
}

__global__ void __launch_bounds__(64) k_build(const float* __restrict__ pred,
                                              const float* __restrict__ target,
                                              const int*   __restrict__ tsizes) {
    const int b = blockIdx.x;
    const int t = threadIdx.x;

    __shared__ int   pos_map[PLANE];
    __shared__ int   lastBest[MAXT * NA];
    __shared__ int   lastIgn[MAXT * NA];
    __shared__ int   s_gi[MAXT], s_gj[MAXT], s_lbl[MAXT], s_cor[MAXT];
    __shared__ float s_tx[MAXT], s_ty[MAXT], s_tw[MAXT], s_th[MAXT];
    __shared__ int   s_cnt;

    if (t == 0) s_cnt = 0;
    if (b == 0) {
        if (t < 12) g_acc[t] = 0.0f;
        if (t == 12) g_done = 0;
    }
    for (int i = t; i < PLANE; i += 64) pos_map[i] = 0x7FFFFFFF;
    for (int i = t; i < MAXT * NA; i += 64) { lastBest[i] = -1; lastIgn[i] = -1; }
    __syncthreads();

    int ts = tsizes[b];
    if (ts > MAXT) ts = MAXT;

    const float AW[5] = {1.f, 2.f, 4.f, 2.f, 4.f};
    const float AH[5] = {1.f, 2.f, 4.f, 4.f, 2.f};

    if (t < ts) {
        const float* row = target + ((long)(b * MAXT + t)) * (13 + NCLS);
        float gx = row[0] * (1.0f / 16.0f);
        float gy = row[1] * (1.0f / 16.0f);
        float gh = row[3] * (1.0f / 16.0f);
        float gw = row[4] * (1.0f / 16.0f);
        int gi = (int)gx;
        int gj = (int)gy;
        int pos = gj * NW + gi;

        atomicMin(&pos_map[pos], t);

        int lbl = 0; float bv = row[13];
        #pragma unroll
        for (int c = 1; c < NCLS; c++) {
            float v = row[13 + c];
            if (v > bv) { bv = v; lbl = c; }
        }

        float garea = (gw + 1.0f) * (gh + 1.0f);
        float best_iou = -1.0f; int best = 0; unsigned ign = 0u;
        #pragma unroll
        for (int a = 0; a < 5; a++) {
            float iw = fmaxf(fminf(gw, AW[a]) + 1.0f, 0.0f);
            float ih = fmaxf(fminf(gh, AH[a]) + 1.0f, 0.0f);
            float inter = iw * ih;
            float aa = (AW[a] + 1.0f) * (AH[a] + 1.0f);
            float iou = inter / (garea + aa - inter + 1e-16f);
            if (iou > 0.5f) ign |= (1u << a);
            if (iou > best_iou) { best_iou = iou; best = a; }  // first-max tie
        }

        s_gi[t] = gi; s_gj[t] = gj; s_lbl[t] = lbl;
        s_tx[t] = gx - (float)gi;
        s_ty[t] = gy - (float)gj;
        s_tw[t] = logf(gw / AW[best] + 1e-16f);
        s_th[t] = logf(gh / AH[best] + 1e-16f);
        s_cor[t] = (int)ign | (best << 8) | (pos << 16);

        long base = ((((long)b * NA + best) * NH + gj) * NW + gi) * CH;
        float pc = pred[base + 0];
        float x = pred[base + 1], y = pred[base + 2];
        float h = pred[base + 3], w = pred[base + 4];
        float px = x + (float)gi, py = y + (float)gj;
        float pw = expf(w) * AW[best];
        float ph = expf(h) * AH[best];

        float gx1 = gx - gw * 0.5f, gx2 = gx + gw * 0.5f;
        float gy1 = gy - gh * 0.5f, gy2 = gy + gh * 0.5f;
        float px1 = px - pw * 0.5f, px2 = px + pw * 0.5f;
        float py1 = py - ph * 0.5f, py2 = py + ph * 0.5f;
        float iw2 = fmaxf(fminf(gx2, px2) - fmaxf(gx1, px1) + 1.0f, 0.0f);
        float ih2 = fmaxf(fminf(gy2, py2) - fmaxf(gy1, py1) + 1.0f, 0.0f);
        float inter2 = iw2 * ih2;
        float ga = (gx2 - gx1 + 1.0f) * (gy2 - gy1 + 1.0f);
        float pa = (px2 - px1 + 1.0f) * (py2 - py1 + 1.0f);
        float iou2 = inter2 / (ga + pa - inter2 + 1e-16f);

        int cb = 0; float cbv = pred[base + 5];
        #pragma unroll
        for (int c = 1; c < NCLS; c++) {
            float v = pred[base + 5 + c];
            if (v > cbv) { cbv = v; cb = c; }
        }
        int correct = (iou2 > 0.5f && cb == lbl && pc > 0.5f) ? 1 : 0;
        s_cor[t] |= (correct << 30);
    }
    __syncthreads();

    if (t < ts) {
        int pk   = s_cor[t];
        int pos  = (pk >> 16) & 0x3FFF;
        int best = (pk >> 8) & 0x1F;
        unsigned ign = (unsigned)(pk & 0xFF);
        int slot = pos_map[pos];
        atomicMax(&lastBest[slot * NA + best], t);
        #pragma unroll
        for (int a = 0; a < 5; a++)
            if ((ign >> a) & 1u) atomicMax(&lastIgn[slot * NA + a], t);
    }
    __syncthreads();

    if (t < ts) {
        int pos = s_gj[t] * NW + s_gi[t];
        if (pos_map[pos] == t) {
            #pragma unroll
            for (int a = 0; a < 5; a++) {
                int lb = lastBest[t * NA + a];
                int li = lastIgn[t * NA + a];
                if (lb >= 0) {
                    int cm = (lb >= li) ? 1 : 0;
                    int idx = atomicAdd(&s_cnt, 1);
                    int gidx = b * MAXE + idx;
                    g_ecell[gidx] = b * (NA * PLANE) + a * PLANE + pos;
                    g_einfo[gidx] = 1 | (cm << 1) | (s_lbl[lb] << 2);
                    g_etx[gidx] = s_tx[lb]; g_ety[gidx] = s_ty[lb];
                    g_etw[gidx] = s_tw[lb]; g_eth[gidx] = s_th[lb];
                } else if (li >= 0) {
                    int idx = atomicAdd(&s_cnt, 1);
                    int gidx = b * MAXE + idx;
                    g_ecell[gidx] = b * (NA * PLANE) + a * PLANE + pos;
                    g_einfo[gidx] = 0;
                }
            }
        }
    }
    __syncthreads();

    if (t == 0) {
        g_ecnt[b] = s_cnt;
        int nC = 0;
        for (int i = 0; i < ts; i++) nC += (s_cor[i] >> 30) & 1;
        g_nGT[b] = (float)ts;
        g_nC[b]  = (float)nC;
    }
}

__global__ void __launch_bounds__(MAIN_THREADS) k_main(const float* __restrict__ pred,
                                                       float* __restrict__ out) {
    __shared__ float red[WARPS_PER_BLOCK][10];
    const int lane = threadIdx.x & 31;
    const int warp = threadIdx.x >> 5;

    if (blockIdx.x >= CORR_BLOCKS) {
        // ---- sweep: 1 cell/thread, coherent-path scalar load (NOT ld.global.nc) ----
        const int cell = (blockIdx.x - CORR_BLOCKS) * MAIN_THREADS + threadIdx.x;
        float pc = ldg_coherent(pred + (size_t)cell * CH);
        float neg = fmaxf(pc, 0.0f) + log1pf(expf(-fabsf(pc)));
        float np  = (pc > 0.0f) ? 1.0f : 0.0f;

        #pragma unroll
        for (int off = 16; off > 0; off >>= 1) {
            neg += __shfl_down_sync(0xFFFFFFFFu, neg, off);
            np  += __shfl_down_sync(0xFFFFFFFFu, np, off);
        }
        if (lane == 0) { red[warp][0] = neg; red[warp][1] = np; }
        __syncthreads();
        if (threadIdx.x == 0) {
            float sn = 0.0f, sp = 0.0f;
            #pragma unroll
            for (int w = 0; w < WARPS_PER_BLOCK; w++) { sn += red[w][0]; sp += red[w][1]; }
            atomicAdd(&g_acc[4], sn);
            atomicAdd(&g_acc[9], sp);
        }
    } else {
        // ---- correction path: exact deltas vs default (m=0, cm=1) ----
        float acc[10];
        #pragma unroll
        for (int k = 0; k < 10; k++) acc[k] = 0.0f;

        const int tid = blockIdx.x * MAIN_THREADS + threadIdx.x;
        const int stride = CORR_BLOCKS * MAIN_THREADS;
        for (int b = 0; b < NB; b++) {
            int cnt = g_ecnt[b];
            for (int i = tid; i < cnt; i += stride) {
                int gidx = b * MAXE + i;
                int cell = g_ecell[gidx];
                int info = g_einfo[gidx];
                const float* p = pred + (size_t)cell * CH;
                float pc = ldg_coherent(p);
                float bce0 = fmaxf(pc, 0.0f) + log1pf(expf(-fabsf(pc)));
                if (info & 1) {
                    float bce1 = bce0 - pc;
                    if ((info >> 1) & 1) { acc[4] -= bce0; acc[5] -= 1.0f; }
                    else                 { acc[4] += bce1 - bce0; }
                    acc[6] += bce1;
                    acc[7] += 1.0f;
                    float dx = ldg_coherent(p + 1) - g_etx[gidx]; acc[0] += dx * dx;
                    float dy = ldg_coherent(p + 2) - g_ety[gidx]; acc[1] += dy * dy;
                    float dw = ldg_coherent(p + 4) - g_etw[gidx]; acc[2] += dw * dw;
                    float dh = ldg_coherent(p + 3) - g_eth[gidx]; acc[3] += dh * dh;
                    int lbl = info >> 2;
                    float mx = -FLT_MAX;
                    for (int c = 0; c < NCLS; c++) mx = fmaxf(mx, ldg_coherent(p + 5 + c));
                    float sxp = 0.0f;
                    for (int c = 0; c < NCLS; c++) sxp += expf(ldg_coherent(p + 5 + c) - mx);
                    acc[8] += -(ldg_coherent(p + 5 + lbl) - mx - logf(sxp));
                } else {
                    acc[4] -= bce0; acc[5] -= 1.0f;
                }
            }
        }

        #pragma unroll
        for (int k = 0; k < 10; k++) {
            float x = acc[k];
            #pragma unroll
            for (int off = 16; off > 0; off >>= 1)
                x += __shfl_down_sync(0xFFFFFFFFu, x, off);
            if (lane == 0) red[warp][k] = x;
        }
        __syncthreads();
        if (threadIdx.x == 0) {
            #pragma unroll
            for (int k = 0; k < 10; k++) {
                float x = 0.0f;
                #pragma unroll
                for (int w = 0; w < WARPS_PER_BLOCK; w++) x += red[w][k];
                if (x != 0.0f) atomicAdd(&g_acc[k], x);
            }
        }
    }

    // ---- last-block-done finalization ----
    if (threadIdx.x == 0) {
        __threadfence();
        int old = atomicAdd(&g_done, 1);
        if (old == TOTAL_BLOCKS - 1) {
            volatile float* A = g_acc;
            float nM = A[7];
            float lx = A[0] / nM, ly = A[1] / nM, lw = A[2] / nM, lh = A[3] / nM;
            float neg_cnt = (float)NCELL + A[5];
            float lconf = A[4] / neg_cnt + A[6] / nM;
            float lcls = (1.0f / (float)NB) * A[8] / nM;
            float nGT = 0.0f, nC = 0.0f;
            for (int b = 0; b < NB; b++) { nGT += g_nGT[b]; nC += g_nC[b]; }
            float nP = A[9];
            out[0] = lx + ly + lw + lh + lconf + lcls;
            out[1] = lx + ly + lw + lh;
            out[2] = lconf;
            out[3] = lcls;
            out[4] = nC / fmaxf(nGT, 1.0f);
            out[5] = (nP > 0.0f) ? (nC / fmaxf(nP, 1.0f)) : 1.0f;
        }
    }
}

extern "C" void kernel_launch(void* const* d_in, const int* in_sizes, int n_in,
                              void* d_out, int out_size) {
    const float* pred   = (const float*)d_in[0];
    const float* target = (const float*)d_in[1];
    const int*   tsz    = (const int*)d_in[2];
    float* out = (float*)d_out;
    (void)in_sizes; (void)n_in; (void)out_size;

    k_build<<<NB, 64>>>(pred, target, tsz);
    k_main<<<TOTAL_BLOCKS, MAIN_THREADS>>>(pred, out);
}

// round 14
// speedup vs baseline: 3.6448x; 2.4883x over previous
#include <cuda_runtime.h>
#include <math.h>
#include <float.h>

#define NB 16
#define NA 5
#define NH 96
#define NW 96
#define MAXT 50
#define NCLS 40
#define CH (5 + NCLS)          // 45
#define NCELL (NB*NA*NH*NW)    // 737280
#define PLANE (NH*NW)          // 9216

#define SWEEP_BLOCKS ((NCELL + 255) / 256)   // 2880

// Device scratch (no allocations allowed) — R1 layout
__device__ float g_mask[NCELL];
__device__ float g_cmask[NCELL];
__device__ float g_tx[NCELL];
__device__ float g_ty[NCELL];
__device__ float g_tw[NCELL];
__device__ float g_th[NCELL];
__device__ int   g_tlabel[NCELL];
// acc: 0 sx,1 sy,2 sw,3 sh,4 neg_sum,5 neg_cnt,6 pos_sum,7 nM,8 cls_sum,9 nProp,10 nGT,11 nCorrect
__device__ float g_acc[16];
__device__ int   g_done;

__global__ void k_init() {
    int i = blockIdx.x * blockDim.x + threadIdx.x;
    if (i < NCELL) {
        g_mask[i]  = 0.0f;
        g_cmask[i] = 1.0f;
    }
    if (i < 16) g_acc[i] = 0.0f;
    if (i == 16) g_done = 0;
}

__global__ void k_build(const float* __restrict__ pred,
                        const float* __restrict__ target,
                        const int*   __restrict__ tsizes) {
    const int b = blockIdx.x;
    const int t = threadIdx.x;

    __shared__ int   s_gi[MAXT], s_gj[MAXT], s_best[MAXT], s_lbl[MAXT], s_cor[MAXT];
    __shared__ float s_tx[MAXT], s_ty[MAXT], s_tw[MAXT], s_th[MAXT];
    __shared__ unsigned s_ign[MAXT];

    int ts = tsizes[b];
    if (ts > MAXT) ts = MAXT;

    const float AW[5] = {1.f, 2.f, 4.f, 2.f, 4.f};
    const float AH[5] = {1.f, 2.f, 4.f, 4.f, 2.f};

    if (t < MAXT && t < ts) {
        const float* row = target + ((long)(b * MAXT + t)) * (13 + NCLS);
        float gx = row[0] * (1.0f / 16.0f);
        float gy = row[1] * (1.0f / 16.0f);
        float gh = row[3] * (1.0f / 16.0f);
        float gw = row[4] * (1.0f / 16.0f);
        int gi = (int)gx;
        int gj = (int)gy;

        // label = argmax over one-hot (first max)
        int lbl = 0; float bv = row[13];
        #pragma unroll
        for (int c = 1; c < NCLS; c++) {
            float v = row[13 + c];
            if (v > bv) { bv = v; lbl = c; }
        }

        // anchor IoUs
        float garea = (gw + 1.0f) * (gh + 1.0f);
        float best_iou = -1.0f; int best = 0; unsigned ign = 0u;
        #pragma unroll
        for (int a = 0; a < 5; a++) {
            float iw = fminf(gw, AW[a]) + 1.0f; iw = fmaxf(iw, 0.0f);
            float ih = fminf(gh, AH[a]) + 1.0f; ih = fmaxf(ih, 0.0f);
            float inter = iw * ih;
            float aa = (AW[a] + 1.0f) * (AH[a] + 1.0f);
            float iou = inter / (garea + aa - inter + 1e-16f);
            if (iou > 0.5f) ign |= (1u << a);
            if (iou > best_iou) { best_iou = iou; best = a; }  // first-max tie rule
        }

        s_gi[t] = gi; s_gj[t] = gj; s_best[t] = best; s_lbl[t] = lbl; s_ign[t] = ign;
        s_tx[t] = gx - (float)gi;
        s_ty[t] = gy - (float)gj;
        s_tw[t] = logf(gw / AW[best] + 1e-16f);
        s_th[t] = logf(gh / AH[best] + 1e-16f);

        // prediction at best cell (for nCorrect)
        long base = ((((long)b * NA + best) * NH + gj) * NW + gi) * CH;
        float pc = pred[base + 0];
        float x = pred[base + 1], y = pred[base + 2];
        float h = pred[base + 3], w = pred[base + 4];
        float px = x + (float)gi, py = y + (float)gj;
        float pw = expf(w) * AW[best];
        float ph = expf(h) * AH[best];

        float gx1 = gx - gw * 0.5f, gx2 = gx + gw * 0.5f;
        float gy1 = gy - gh * 0.5f, gy2 = gy + gh * 0.5f;
        float px1 = px - pw * 0.5f, px2 = px + pw * 0.5f;
        float py1 = py - ph * 0.5f, py2 = py + ph * 0.5f;
        float iw2 = fmaxf(fminf(gx2, px2) - fmaxf(gx1, px1) + 1.0f, 0.0f);
        float ih2 = fmaxf(fminf(gy2, py2) - fmaxf(gy1, py1) + 1.0f, 0.0f);
        float inter2 = iw2 * ih2;
        float ga = (gx2 - gx1 + 1.0f) * (gy2 - gy1 + 1.0f);
        float pa = (px2 - px1 + 1.0f) * (py2 - py1 + 1.0f);
        float iou2 = inter2 / (ga + pa - inter2 + 1e-16f);

        // pred class argmax (first max)
        int cb = 0; float cbv = pred[base + 5];
        #pragma unroll
        for (int c = 1; c < NCLS; c++) {
            float v = pred[base + 5 + c];
            if (v > cbv) { cbv = v; cb = c; }
        }
        s_cor[t] = (iou2 > 0.5f && cb == lbl && pc > 0.5f) ? 1 : 0;
    }
    __syncthreads();

    // Serial replay of map writes (ordering matters for collisions)
    if (t == 0) {
        int nGT = 0, nC = 0;
        for (int i = 0; i < ts; i++) {
            nGT++; nC += s_cor[i];
            int gi = s_gi[i], gj = s_gj[i], best = s_best[i];
            long col = (((long)b * NA) * NH + gj) * NW + gi;  // anchor 0
            unsigned ign = s_ign[i];
            #pragma unroll
            for (int a = 0; a < 5; a++)
                if ((ign >> a) & 1u) g_cmask[col + (long)a * PLANE] = 0.0f;
            long ib = col + (long)best * PLANE;
            g_cmask[ib] = 1.0f;
            g_mask[ib]  = 1.0f;
            g_tx[ib] = s_tx[i];
            g_ty[ib] = s_ty[i];
            g_tw[ib] = s_tw[i];
            g_th[ib] = s_th[i];
            g_tlabel[ib] = s_lbl[i];
        }
        atomicAdd(&g_acc[10], (float)nGT);
        atomicAdd(&g_acc[11], (float)nC);
    }
}

__global__ void k_sweep(const float* __restrict__ pred, float* __restrict__ out) {
    const int cell = blockIdx.x * blockDim.x + threadIdx.x;

    float v[10]; // sx,sy,sw,sh,neg,negc,pos,nm,scls,nprop
    #pragma unroll
    for (int k = 0; k < 10; k++) v[k] = 0.0f;

    if (cell < NCELL) {
        float m  = g_mask[cell];
        float cm = g_cmask[cell];
        const float* p = pred + (long)cell * CH;
        float pc = p[0];
        float bce = fmaxf(pc, 0.0f) - pc * m + log1pf(expf(-fabsf(pc)));
        if (cm != m) { v[4] = bce; v[5] = 1.0f; }
        v[6] = m * bce;
        v[7] = m;
        v[9] = (pc > 0.0f) ? 1.0f : 0.0f;
        if (m != 0.0f) {
            float x = p[1], y = p[2], h = p[3], w = p[4];
            float dx = x - g_tx[cell]; v[0] = dx * dx;
            float dy = y - g_ty[cell]; v[1] = dy * dy;
            float dw = w - g_tw[cell]; v[2] = dw * dw;
            float dh = h - g_th[cell]; v[3] = dh * dh;
            int lbl = g_tlabel[cell];
            float mx = -FLT_MAX;
            for (int c = 0; c < NCLS; c++) mx = fmaxf(mx, p[5 + c]);
            float s = 0.0f;
            for (int c = 0; c < NCLS; c++) s += expf(p[5 + c] - mx);
            v[8] = -(p[5 + lbl] - mx - logf(s));
        }
    }

    // block reduce 10 accumulators
    __shared__ float red[8][10];
    int lane = threadIdx.x & 31;
    int warp = threadIdx.x >> 5;
    #pragma unroll
    for (int k = 0; k < 10; k++) {
        float x = v[k];
        #pragma unroll
        for (int off = 16; off > 0; off >>= 1)
            x += __shfl_down_sync(0xFFFFFFFFu, x, off);
        if (lane == 0) red[warp][k] = x;
    }
    __syncthreads();
    if (warp == 0 && lane == 0) {
        #pragma unroll
        for (int k = 0; k < 10; k++) {
            float x = 0.0f;
            #pragma unroll
            for (int w = 0; w < 8; w++) x += red[w][k];
            if (x != 0.0f) atomicAdd(&g_acc[k], x);
        }
        __threadfence();
        int old = atomicAdd(&g_done, 1);
        if (old == SWEEP_BLOCKS - 1) {
            // fused finalization: all sweep blocks' g_acc updates are visible
            volatile float* A = g_acc;
            float nM = A[7];
            float lx = A[0] / nM;
            float ly = A[1] / nM;
            float lw = A[2] / nM;
            float lh = A[3] / nM;
            float lcoord = lx + ly + lw + lh;
            float lconf = A[4] / A[5] + A[6] / nM;
            float lcls = (1.0f / (float)NB) * A[8] / nM;
            float loss = lx + ly + lw + lh + lconf + lcls;
            float nGT = A[10], nC = A[11], nP = A[9];
            out[0] = loss;
            out[1] = lcoord;
            out[2] = lconf;
            out[3] = lcls;
            out[4] = nC / fmaxf(nGT, 1.0f);
            out[5] = (nP > 0.0f) ? (nC / fmaxf(nP, 1.0f)) : 1.0f;
        }
    }
}

extern "C" void kernel_launch(void* const* d_in, const int* in_sizes, int n_in,
                              void* d_out, int out_size) {
    const float* pred   = (const float*)d_in[0];
    const float* target = (const float*)d_in[1];
    const int*   tsz    = (const int*)d_in[2];
    float* out = (float*)d_out;

    (void)in_sizes; (void)n_in; (void)out_size;

    k_init<<<SWEEP_BLOCKS, 256>>>();
    k_build<<<NB, 64>>>(pred, target, tsz);
    k_sweep<<<SWEEP_BLOCKS, 256>>>(pred, out);
}